// round 6
// baseline (speedup 1.0000x reference)
#include <cuda_runtime.h>
#include <cstdint>

// RipsH1 edge-length gather — pair-cooperative, persistent warps with
// software-prefetched index rows.
//
// Flat distance list, D = e0 + 2*e1:
//   t <  e0 : (ia, ib) = verts0 row t
//   t >= e0 : (ia, ib) = ((int2*)verts1)[t - e0]
//   out[t]  = || pts[ia] - pts[ib] ||      (8-dim)
//
// - 2 lanes per distance (lane h owns float4 half h; the halves share one 32B
//   sector -> 1 L1 wavefront per point).
// - U=4 distances per lane-pair per iteration, gathers front-batched.
// - Grid-stride loop: while iteration i's gathers are in flight, the warp
//   issues the index loads for iteration i+1 (33MB index stream comes from
//   DRAM at ~577cyc; previously this serialized ahead of every gather batch).
// - Index loads / output stores use .cg (zero-reuse streams; keep L1 for the
//   2MB points table).

static constexpr int DIM_F4   = 2;      // 8 floats = 2 float4
static constexpr int IDX_MASK = 0xFFFF; // N_POINTS = 65536
static constexpr int U        = 4;      // distances per lane-pair per iter
static constexpr int DIST_PER_WARP = 16 * U;  // 64

__device__ __forceinline__ int2 ldcg_int2(const int2* p) {
    int2 r;
    asm volatile("ld.global.cg.v2.s32 {%0, %1}, [%2];"
                 : "=r"(r.x), "=r"(r.y) : "l"(p));
    return r;
}

__device__ __forceinline__ void stcg_f32(float* p, float v) {
    asm volatile("st.global.cg.f32 [%0], %1;" :: "l"(p), "f"(v));
}

__device__ __forceinline__ int2 load_idx(const int2* __restrict__ v0,
                                         const int2* __restrict__ v1p,
                                         int tt, int e0, int total) {
    tt = (tt < total) ? tt : (total - 1);   // clamp: always a safe address
    return (tt < e0) ? ldcg_int2(v0 + tt) : ldcg_int2(v1p + (tt - e0));
}

__global__ __launch_bounds__(256, 4)
void rips_persist_kernel(const float4* __restrict__ pts,
                         const int2* __restrict__ v0,   // e0 rows of 2 i32
                         const int2* __restrict__ v1p,  // verts1 as 2*e1 int2 pairs
                         float* __restrict__ out,
                         int e0, int total, int stride_dist) {
    const int gtid = blockIdx.x * blockDim.x + threadIdx.x;
    const int warp = gtid >> 5;
    const int lane = gtid & 31;
    const int pair = lane >> 1;   // 0..15
    const int h    = lane & 1;    // float4 half owned by this lane

    const int t0 = warp * DIST_PER_WARP + pair;

    // Prologue: prefetch indices for the first tile.
    int2 pidx[U];
#pragma unroll
    for (int u = 0; u < U; u++)
        pidx[u] = load_idx(v0, v1p, t0 + u * 16, e0, total);

    for (int tbase = t0; tbase < total; tbase += stride_dist) {
        // ---- consume prefetched indices ----
        int tcur[U], ia[U], ib[U];
#pragma unroll
        for (int u = 0; u < U; u++) {
            tcur[u] = tbase + u * 16;
            ia[u] = pidx[u].x & IDX_MASK;
            ib[u] = pidx[u].y & IDX_MASK;
        }

        // ---- issue gathers (8 independent LDG.128 in flight) ----
        float4 a[U], b[U];
#pragma unroll
        for (int u = 0; u < U; u++) {
            a[u] = __ldg(pts + ia[u] * DIM_F4 + h);
            b[u] = __ldg(pts + ib[u] * DIM_F4 + h);
        }

        // ---- prefetch next tile's indices (overlaps gather latency) ----
        const int tnext = tbase + stride_dist;
#pragma unroll
        for (int u = 0; u < U; u++)
            pidx[u] = load_idx(v0, v1p, tnext + u * 16, e0, total);

        // ---- math + pair-combine + store ----
#pragma unroll
        for (int u = 0; u < U; u++) {
            float dx, s;
            dx = a[u].x - b[u].x; s = dx * dx;
            dx = a[u].y - b[u].y; s = fmaf(dx, dx, s);
            dx = a[u].z - b[u].z; s = fmaf(dx, dx, s);
            dx = a[u].w - b[u].w; s = fmaf(dx, dx, s);
            s += __shfl_xor_sync(0xFFFFFFFF, s, 1);
            if (tcur[u] < total && h == 0)
                stcg_f32(out + tcur[u], sqrtf(s));
        }
    }
}

extern "C" void kernel_launch(void* const* d_in, const int* in_sizes, int n_in,
                              void* d_out, int out_size) {
    const float4* pts = (const float4*)d_in[0];
    const int2*   v0  = (const int2*)d_in[1];
    const int2*   v1p = (const int2*)d_in[2];
    float*        out = (float*)d_out;

    const int e0 = in_sizes[1] / 2;          // verts0 rows
    const int e1 = in_sizes[2] / 4;          // verts1 rows
    const int total = e0 + 2 * e1;           // flat distance count

    // Persistent-ish grid: 4 CTAs/SM on 148 SMs; each warp strides the list.
    const int threads = 256;
    const int blocks  = 148 * 4;
    const int warps   = blocks * (threads / 32);
    const int stride_dist = warps * DIST_PER_WARP;

    rips_persist_kernel<<<blocks, threads>>>(pts, v0, v1p, out,
                                             e0, total, stride_dist);
}